// round 5
// baseline (speedup 1.0000x reference)
#include <cuda_runtime.h>
#include <cuda_bf16.h>

// ---------------------------------------------------------------------------
// RIMDLoss fused loss.
// total = recon + 0.1*lap + 0.01*drift + 0.1*arap + beta*kl
//
// R1: final composition was 92us (serial fp64 divide chains in one thread).
// R4: final phase still 24us -> root cause: 1 block reading 64KB mu/logvar
//     cold from DRAM, latency-bound. Fix: fold KL into the wide node pass;
//     composition kernel touches only device accumulators.
// Edge pass (~120us) sits at the L1tex-wavefront / L2-sector floor for
// 32M random 32B-sector gathers; left unchanged.
// ---------------------------------------------------------------------------

#define NUM_GRAPHS 64

__device__ double g_recon;   // sum (p-t)^2 over all elements
__device__ double g_lap;     // sum d2 over edges  (== sum len^2)
__device__ double g_len;     // sum len over edges
__device__ double g_kl;      // sum (1 + lv - mu^2 - exp(lv)) over G*L
__device__ float  g_sumx[NUM_GRAPHS];
__device__ float  g_sumy[NUM_GRAPHS];
__device__ float  g_cnt [NUM_GRAPHS];

__global__ void init_kernel() {
    int t = threadIdx.x;
    if (t == 0) { g_recon = 0.0; g_lap = 0.0; g_len = 0.0; g_kl = 0.0; }
    if (t < NUM_GRAPHS) { g_sumx[t] = 0.f; g_sumy[t] = 0.f; g_cnt[t] = 0.f; }
}

__device__ __forceinline__ float warpReduceF(float v) {
    #pragma unroll
    for (int o = 16; o; o >>= 1) v += __shfl_down_sync(0xffffffffu, v, o);
    return v;
}
__device__ __forceinline__ double warpReduceD(double v) {
    #pragma unroll
    for (int o = 16; o; o >>= 1) v += __shfl_down_sync(0xffffffffu, v, o);
    return v;
}

// Block-reduce a double and atomically add into *dst.
__device__ __forceinline__ void blockAtomicAddD(double v, double* dst, double* sh) {
    int lane = threadIdx.x & 31;
    int wid  = threadIdx.x >> 5;
    v = warpReduceD(v);
    if (lane == 0) sh[wid] = v;
    __syncthreads();
    int nw = (blockDim.x + 31) >> 5;
    if (wid == 0) {
        double x = (lane < nw) ? sh[lane] : 0.0;
        x = warpReduceD(x);
        if (lane == 0) atomicAdd(dst, x);
    }
    __syncthreads();
}

// ---------------------------------------------------------------------------
// Node pass: recon partials + per-graph (sum, count) via warp-aggregated
// atomics (batch sorted -> warps almost always graph-uniform) + KL partials
// folded in (blocks 0..31 cover the 8K-element mu/logvar sum; the node pass
// is DRAM-wide so this extra 64KB read is latency-hidden, unlike R4's
// single-block version).
// ---------------------------------------------------------------------------
__global__ void node_kernel(const float2* __restrict__ pred,
                            const float2* __restrict__ targ,
                            const int*    __restrict__ batch,
                            const float*  __restrict__ mu,
                            const float*  __restrict__ logvar,
                            int N, int GL) {
    __shared__ double sh[32];
    int lane   = threadIdx.x & 31;
    int gwid   = (blockIdx.x * blockDim.x + threadIdx.x) >> 5;
    int nwarps = (gridDim.x * blockDim.x) >> 5;

    float racc = 0.f;
    for (long long base = (long long)gwid * 32; base < N; base += (long long)nwarps * 32) {
        int idx   = (int)base + lane;
        bool valid = idx < N;
        float2 p = valid ? pred[idx] : make_float2(0.f, 0.f);
        if (valid) {
            float2 t = __ldcs(&targ[idx]);
            float dx = p.x - t.x, dy = p.y - t.y;
            racc += dx * dx + dy * dy;
        }
        int g  = valid ? __ldcs(&batch[idx]) : -1;
        int g0 = __shfl_sync(0xffffffffu, g, 0);
        unsigned vm = __ballot_sync(0xffffffffu, valid);
        bool uniform = __all_sync(0xffffffffu, (!valid) || (g == g0));
        if (uniform) {
            float sx = warpReduceF(valid ? p.x : 0.f);
            float sy = warpReduceF(valid ? p.y : 0.f);
            if (lane == 0 && vm) {
                atomicAdd(&g_sumx[g0], sx);
                atomicAdd(&g_sumy[g0], sy);
                atomicAdd(&g_cnt [g0], (float)__popc(vm));
            }
        } else if (valid) {   // rare: warp straddles a graph boundary
            atomicAdd(&g_sumx[g], p.x);
            atomicAdd(&g_sumy[g], p.y);
            atomicAdd(&g_cnt [g], 1.f);
        }
    }
    blockAtomicAddD((double)racc, &g_recon, sh);

    // KL fold-in: first 32 blocks stride the GL elements (8192 / (32*256) = 1 each)
    if (blockIdx.x < 32) {
        float kacc = 0.f;
        for (int i = blockIdx.x * blockDim.x + threadIdx.x; i < GL; i += 32 * blockDim.x) {
            float lv = logvar[i];
            float m  = mu[i];
            kacc += 1.0f + lv - m * m - __expf(lv);
        }
        blockAtomicAddD((double)kacc, &g_kl, sh);
    }
}

// ---------------------------------------------------------------------------
// Edge pass: int4 index reads with evict-first hint (128MB single-use stream
// must not thrash pred's 8MB L2 working set); random float2 gathers
// (L2-resident). len^2 == d2, so one accumulator serves both Laplacian and
// ARAP's second moment.
// ---------------------------------------------------------------------------
__global__ void edge_kernel(const float2* __restrict__ pred,
                            const int*    __restrict__ ei,  // row 0; row 1 at ei+E
                            int E) {
    __shared__ double sh2[32];
    __shared__ double shl[32];
    const int* ej = ei + E;

    int tid    = blockIdx.x * blockDim.x + threadIdx.x;
    int stride = gridDim.x * blockDim.x;

    float s2 = 0.f, sl = 0.f;

    int E4 = E >> 2;
    const int4* ei4 = (const int4*)ei;
    const int4* ej4 = (const int4*)ej;

    for (int k = tid; k < E4; k += stride) {
        int4 a = __ldcs(&ei4[k]);
        int4 b = __ldcs(&ej4[k]);
        float2 pa0 = __ldg(&pred[a.x]); float2 pb0 = __ldg(&pred[b.x]);
        float2 pa1 = __ldg(&pred[a.y]); float2 pb1 = __ldg(&pred[b.y]);
        float2 pa2 = __ldg(&pred[a.z]); float2 pb2 = __ldg(&pred[b.z]);
        float2 pa3 = __ldg(&pred[a.w]); float2 pb3 = __ldg(&pred[b.w]);

        float dx0 = pa0.x - pb0.x, dy0 = pa0.y - pb0.y;
        float dx1 = pa1.x - pb1.x, dy1 = pa1.y - pb1.y;
        float dx2 = pa2.x - pb2.x, dy2 = pa2.y - pb2.y;
        float dx3 = pa3.x - pb3.x, dy3 = pa3.y - pb3.y;

        float d0 = dx0 * dx0 + dy0 * dy0;
        float d1 = dx1 * dx1 + dy1 * dy1;
        float d2 = dx2 * dx2 + dy2 * dy2;
        float d3 = dx3 * dx3 + dy3 * dy3;

        s2 += (d0 + d1) + (d2 + d3);
        sl += (sqrtf(d0) + sqrtf(d1)) + (sqrtf(d2) + sqrtf(d3));
    }
    for (int k = (E4 << 2) + tid; k < E; k += stride) {   // tail (E % 4)
        float2 pa = __ldg(&pred[__ldcs(&ei[k])]);
        float2 pb = __ldg(&pred[__ldcs(&ej[k])]);
        float dx = pa.x - pb.x, dy = pa.y - pb.y;
        float d = dx * dx + dy * dy;
        s2 += d;
        sl += sqrtf(d);
    }

    blockAtomicAddD((double)s2, &g_lap, sh2);
    blockAtomicAddD((double)sl, &g_len, shl);
}

// ---------------------------------------------------------------------------
// Compose: touches ONLY device accumulators (no DRAM input reads).
// 64 threads: drift divides in parallel, warp-reduce, thread 0 finalizes.
// ---------------------------------------------------------------------------
__global__ void compose_kernel(const int* __restrict__ epoch_ptr,
                               float* __restrict__ out,
                               int E, int N) {
    __shared__ float shd[2];
    int lane = threadIdx.x & 31;
    int wid  = threadIdx.x >> 5;

    // Drift: one graph per thread (64 threads), float division (MUFU-fast)
    {
        int g = threadIdx.x;
        float inv = 1.0f / g_cnt[g];
        float mx = g_sumx[g] * inv;
        float my = g_sumy[g] * inv;
        float d  = mx * mx + my * my;
        d = warpReduceF(d);
        if (lane == 0) shd[wid] = d;
    }
    __syncthreads();

    if (threadIdx.x == 0) {
        float drift = (shd[0] + shd[1]) / (float)NUM_GRAPHS;
        float kl    = -0.5f * (float)g_kl / (float)NUM_GRAPHS;

        float S2 = (float)g_lap;
        float S1 = (float)g_len;
        float fE = (float)E;
        float recon = (float)g_recon / (2.0f * (float)N);
        float lap   = S2 / fE;
        float var   = (S2 - S1 * (S1 / fE)) / (fE - 1.0f);

        int epoch = epoch_ptr ? *epoch_ptr : 5;
        float beta = (epoch < 10) ? ((float)epoch * 0.1f) : 1.0f;

        out[0] = recon + 0.1f * lap + 0.01f * drift + 0.1f * var + beta * kl;
    }
}

// ---------------------------------------------------------------------------
extern "C" void kernel_launch(void* const* d_in, const int* in_sizes, int n_in,
                              void* d_out, int out_size) {
    const float2* pred   = (const float2*)d_in[0];
    const float2* targ   = (const float2*)d_in[1];
    const int*    eidx   = (const int*)   d_in[2];
    const int*    batch  = (const int*)   d_in[3];
    const float*  mu     = (const float*) d_in[4];
    const float*  logvar = (const float*) d_in[5];
    const int*    epoch  = (n_in >= 7) ? (const int*)d_in[6] : nullptr;
    float*        out    = (float*)d_out;

    int N  = in_sizes[0] / 2;       // nodes
    int E  = in_sizes[2] / 2;       // edges
    int GL = in_sizes[4];           // NUM_GRAPHS * LATENT

    init_kernel<<<1, 64>>>();

    {
        int threads = 256;
        int blocks  = (N + threads - 1) / threads;
        if (blocks < 32) blocks = 32;       // KL fold-in needs >= 32 blocks
        if (blocks > 1184) blocks = 1184;
        node_kernel<<<blocks, threads>>>(pred, targ, batch, mu, logvar, N, GL);
    }
    {
        int threads = 256;
        int groups  = (E >> 2) > 0 ? (E >> 2) : 1;
        int blocks  = (groups + threads - 1) / threads;
        if (blocks < 1) blocks = 1;
        if (blocks > 1184) blocks = 1184;   // 148 SMs * 8 blocks = one wave
        edge_kernel<<<blocks, threads>>>(pred, eidx, E);
    }
    compose_kernel<<<1, 64>>>(epoch, out, E, N);
}

// round 6
// speedup vs baseline: 1.0021x; 1.0021x over previous
#include <cuda_runtime.h>
#include <cuda_bf16.h>

// ---------------------------------------------------------------------------
// RIMDLoss fused loss.
// total = recon + 0.1*lap + 0.01*drift + 0.1*arap + beta*kl
//
// R1: final compose 92us (serial fp64 divides). R4: 24us (1-block cold DRAM
// KL). R5: compose fixed (~2us) but total regressed -> launch count + node
// serialization + run variance are the remaining non-edge time.
// R6: TWO launches total.
//   mega_kernel: node pass (recon+drift+KL, DRAM-streaming, ~4us) then edge
//                pass (L1tex-wavefront floor ~105us) in one kernel.
//   compose_kernel: combines, writes out, then RESETS accumulators so the
//                next graph replay starts from zeros (no init kernel; device
//                globals are zero-initialized for the first call).
// ---------------------------------------------------------------------------

#define NUM_GRAPHS 64

__device__ double g_recon;   // sum (p-t)^2 over all elements
__device__ double g_lap;     // sum d2 over edges  (== sum len^2)
__device__ double g_len;     // sum len over edges
__device__ double g_kl;      // sum (1 + lv - mu^2 - exp(lv))
__device__ float  g_sumx[NUM_GRAPHS];
__device__ float  g_sumy[NUM_GRAPHS];
__device__ float  g_cnt [NUM_GRAPHS];

__device__ __forceinline__ float warpReduceF(float v) {
    #pragma unroll
    for (int o = 16; o; o >>= 1) v += __shfl_down_sync(0xffffffffu, v, o);
    return v;
}
__device__ __forceinline__ double warpReduceD(double v) {
    #pragma unroll
    for (int o = 16; o; o >>= 1) v += __shfl_down_sync(0xffffffffu, v, o);
    return v;
}

// Block-reduce a double and atomically add into *dst.
__device__ __forceinline__ void blockAtomicAddD(double v, double* dst, double* sh) {
    int lane = threadIdx.x & 31;
    int wid  = threadIdx.x >> 5;
    v = warpReduceD(v);
    if (lane == 0) sh[wid] = v;
    __syncthreads();
    int nw = (blockDim.x + 31) >> 5;
    if (wid == 0) {
        double x = (lane < nw) ? sh[lane] : 0.0;
        x = warpReduceD(x);
        if (lane == 0) atomicAdd(dst, x);
    }
    __syncthreads();
}

// ---------------------------------------------------------------------------
// Mega kernel: node phase (all blocks, DRAM-streaming) then edge phase
// (all blocks, gather-bound). Accumulators are zero at entry (first call:
// static zero-init; replays: compose_kernel reset).
// ---------------------------------------------------------------------------
__global__ __launch_bounds__(256)
void mega_kernel(const float2* __restrict__ pred,
                 const float2* __restrict__ targ,
                 const int*    __restrict__ batch,
                 const float*  __restrict__ mu,
                 const float*  __restrict__ logvar,
                 const int*    __restrict__ ei,   // row 0; row 1 at ei+E
                 int N, int E, int GL) {
    __shared__ double sh[32];
    __shared__ double shl[32];
    int lane = threadIdx.x & 31;

    // ---------------- node phase: recon + per-graph sums + KL ----------------
    {
        int gwid   = (blockIdx.x * blockDim.x + threadIdx.x) >> 5;
        int nwarps = (gridDim.x * blockDim.x) >> 5;

        float racc = 0.f;
        for (long long base = (long long)gwid * 32; base < N; base += (long long)nwarps * 32) {
            int idx   = (int)base + lane;
            bool valid = idx < N;
            float2 p = valid ? pred[idx] : make_float2(0.f, 0.f);
            if (valid) {
                float2 t = __ldcs(&targ[idx]);
                float dx = p.x - t.x, dy = p.y - t.y;
                racc += dx * dx + dy * dy;
            }
            int g  = valid ? __ldcs(&batch[idx]) : -1;
            int g0 = __shfl_sync(0xffffffffu, g, 0);
            unsigned vm = __ballot_sync(0xffffffffu, valid);
            bool uniform = __all_sync(0xffffffffu, (!valid) || (g == g0));
            if (uniform) {
                float sx = warpReduceF(valid ? p.x : 0.f);
                float sy = warpReduceF(valid ? p.y : 0.f);
                if (lane == 0 && vm) {
                    atomicAdd(&g_sumx[g0], sx);
                    atomicAdd(&g_sumy[g0], sy);
                    atomicAdd(&g_cnt [g0], (float)__popc(vm));
                }
            } else if (valid) {   // rare: warp straddles a graph boundary
                atomicAdd(&g_sumx[g], p.x);
                atomicAdd(&g_sumy[g], p.y);
                atomicAdd(&g_cnt [g], 1.f);
            }
        }
        blockAtomicAddD((double)racc, &g_recon, sh);

        // KL fold-in: first 32 blocks cover GL = 8192 elements (1 elem/thread)
        if (blockIdx.x < 32) {
            float kacc = 0.f;
            for (int i = blockIdx.x * blockDim.x + threadIdx.x; i < GL; i += 32 * blockDim.x) {
                float lv = logvar[i];
                float m  = mu[i];
                kacc += 1.0f + lv - m * m - __expf(lv);
            }
            blockAtomicAddD((double)kacc, &g_kl, sh);
        }
    }

    // ---------------- edge phase: gathers (L1tex-wavefront bound) ------------
    {
        const int* ej = ei + E;
        int tid    = blockIdx.x * blockDim.x + threadIdx.x;
        int stride = gridDim.x * blockDim.x;

        float s2 = 0.f, sl = 0.f;

        int E4 = E >> 2;
        const int4* ei4 = (const int4*)ei;
        const int4* ej4 = (const int4*)ej;

        for (int k = tid; k < E4; k += stride) {
            int4 a = __ldcs(&ei4[k]);
            int4 b = __ldcs(&ej4[k]);
            float2 pa0 = __ldg(&pred[a.x]); float2 pb0 = __ldg(&pred[b.x]);
            float2 pa1 = __ldg(&pred[a.y]); float2 pb1 = __ldg(&pred[b.y]);
            float2 pa2 = __ldg(&pred[a.z]); float2 pb2 = __ldg(&pred[b.z]);
            float2 pa3 = __ldg(&pred[a.w]); float2 pb3 = __ldg(&pred[b.w]);

            float dx0 = pa0.x - pb0.x, dy0 = pa0.y - pb0.y;
            float dx1 = pa1.x - pb1.x, dy1 = pa1.y - pb1.y;
            float dx2 = pa2.x - pb2.x, dy2 = pa2.y - pb2.y;
            float dx3 = pa3.x - pb3.x, dy3 = pa3.y - pb3.y;

            float d0 = dx0 * dx0 + dy0 * dy0;
            float d1 = dx1 * dx1 + dy1 * dy1;
            float d2 = dx2 * dx2 + dy2 * dy2;
            float d3 = dx3 * dx3 + dy3 * dy3;

            s2 += (d0 + d1) + (d2 + d3);
            sl += (sqrtf(d0) + sqrtf(d1)) + (sqrtf(d2) + sqrtf(d3));
        }
        for (int k = (E4 << 2) + tid; k < E; k += stride) {   // tail (E % 4)
            float2 pa = __ldg(&pred[__ldcs(&ei[k])]);
            float2 pb = __ldg(&pred[__ldcs(&ej[k])]);
            float dx = pa.x - pb.x, dy = pa.y - pb.y;
            float d = dx * dx + dy * dy;
            s2 += d;
            sl += sqrtf(d);
        }

        blockAtomicAddD((double)s2, &g_lap, sh);
        blockAtomicAddD((double)sl, &g_len, shl);
    }
}

// ---------------------------------------------------------------------------
// Compose: consume accumulators, write the scalar, then RESET accumulators
// so the next graph replay starts from zeros.
// ---------------------------------------------------------------------------
__global__ void compose_kernel(const int* __restrict__ epoch_ptr,
                               float* __restrict__ out,
                               int E, int N) {
    __shared__ float shd[2];
    int lane = threadIdx.x & 31;
    int wid  = threadIdx.x >> 5;

    // Drift: one graph per thread (64 threads), float division
    {
        int g = threadIdx.x;
        float inv = 1.0f / g_cnt[g];
        float mx = g_sumx[g] * inv;
        float my = g_sumy[g] * inv;
        float d  = mx * mx + my * my;
        d = warpReduceF(d);
        if (lane == 0) shd[wid] = d;
    }
    __syncthreads();

    if (threadIdx.x == 0) {
        float drift = (shd[0] + shd[1]) / (float)NUM_GRAPHS;
        float kl    = -0.5f * (float)g_kl / (float)NUM_GRAPHS;

        float S2 = (float)g_lap;
        float S1 = (float)g_len;
        float fE = (float)E;
        float recon = (float)g_recon / (2.0f * (float)N);
        float lap   = S2 / fE;
        float var   = (S2 - S1 * (S1 / fE)) / (fE - 1.0f);

        int epoch = epoch_ptr ? *epoch_ptr : 5;
        float beta = (epoch < 10) ? ((float)epoch * 0.1f) : 1.0f;

        out[0] = recon + 0.1f * lap + 0.01f * drift + 0.1f * var + beta * kl;

        // reset scalar accumulators (same thread that read them)
        g_recon = 0.0; g_lap = 0.0; g_len = 0.0; g_kl = 0.0;
    }
    __syncthreads();   // all reads of g_sumx/y/cnt happened before this point

    // reset per-graph accumulators for the next replay
    g_sumx[threadIdx.x] = 0.f;
    g_sumy[threadIdx.x] = 0.f;
    g_cnt [threadIdx.x] = 0.f;
}

// ---------------------------------------------------------------------------
extern "C" void kernel_launch(void* const* d_in, const int* in_sizes, int n_in,
                              void* d_out, int out_size) {
    const float2* pred   = (const float2*)d_in[0];
    const float2* targ   = (const float2*)d_in[1];
    const int*    eidx   = (const int*)   d_in[2];
    const int*    batch  = (const int*)   d_in[3];
    const float*  mu     = (const float*) d_in[4];
    const float*  logvar = (const float*) d_in[5];
    const int*    epoch  = (n_in >= 7) ? (const int*)d_in[6] : nullptr;
    float*        out    = (float*)d_out;

    int N  = in_sizes[0] / 2;       // nodes
    int E  = in_sizes[2] / 2;       // edges
    int GL = in_sizes[4];           // NUM_GRAPHS * LATENT

    int threads = 256;
    int blocks  = 1184;             // 148 SMs * 8 blocks = one full wave
    mega_kernel<<<blocks, threads>>>(pred, targ, batch, mu, logvar, eidx, N, E, GL);
    compose_kernel<<<1, 64>>>(epoch, out, E, N);
}

// round 7
// speedup vs baseline: 1.2021x; 1.1996x over previous
#include <cuda_runtime.h>
#include <cuda_bf16.h>

// ---------------------------------------------------------------------------
// RIMDLoss fused loss.
// total = recon + 0.1*lap + 0.01*drift + 0.1*arap + beta*kl
//
// R6 lesson: fusing launches was neutral -> the edge phase itself is ~165us,
// above the ~120us L1tex-wavefront floor. Suspected mechanism: multi-CTA
// spread (MLP_p1~8-12 -> spr_max 1.3-2.0) makes static grid-stride end on the
// slowest CTA, plus the node phase serializes ~5us in every block.
// R7: dynamic work-stealing over edge chunks (ticket counter) + role-split
// prologue (128 blocks node, 32 blocks KL, rest steal edges immediately).
// ---------------------------------------------------------------------------

#define NUM_GRAPHS 64
#define NODE_BLOCKS 128
#define KL_BLOCKS   32
#define CHUNK       1024   // edge-groups (int4 = 4 edges) per ticket

__device__ double   g_recon;   // sum (p-t)^2 over all elements
__device__ double   g_lap;     // sum d2 over edges  (== sum len^2)
__device__ double   g_len;     // sum len over edges
__device__ double   g_kl;      // sum (1 + lv - mu^2 - exp(lv))
__device__ unsigned g_ticket;  // edge-chunk work-stealing counter
__device__ float    g_sumx[NUM_GRAPHS];
__device__ float    g_sumy[NUM_GRAPHS];
__device__ float    g_cnt [NUM_GRAPHS];

__device__ __forceinline__ float warpReduceF(float v) {
    #pragma unroll
    for (int o = 16; o; o >>= 1) v += __shfl_down_sync(0xffffffffu, v, o);
    return v;
}
__device__ __forceinline__ double warpReduceD(double v) {
    #pragma unroll
    for (int o = 16; o; o >>= 1) v += __shfl_down_sync(0xffffffffu, v, o);
    return v;
}

// Block-reduce a double and atomically add into *dst.
__device__ __forceinline__ void blockAtomicAddD(double v, double* dst, double* sh) {
    int lane = threadIdx.x & 31;
    int wid  = threadIdx.x >> 5;
    v = warpReduceD(v);
    if (lane == 0) sh[wid] = v;
    __syncthreads();
    int nw = (blockDim.x + 31) >> 5;
    if (wid == 0) {
        double x = (lane < nw) ? sh[lane] : 0.0;
        x = warpReduceD(x);
        if (lane == 0) atomicAdd(dst, x);
    }
    __syncthreads();
}

// ---------------------------------------------------------------------------
__global__ __launch_bounds__(256)
void mega_kernel(const float2* __restrict__ pred,
                 const float2* __restrict__ targ,
                 const int*    __restrict__ batch,
                 const float*  __restrict__ mu,
                 const float*  __restrict__ logvar,
                 const int*    __restrict__ ei,   // row 0; row 1 at ei+E
                 int N, int E, int GL) {
    __shared__ double   sh[32];
    __shared__ double   shl[32];
    __shared__ unsigned s_chunk;
    int lane = threadIdx.x & 31;

    // ------------- prologue: role-split node / KL (overlapped with edges) ----
    if (blockIdx.x < NODE_BLOCKS) {
        // node phase: recon partials + per-graph sums (warp-aggregated)
        int gwid   = (blockIdx.x * blockDim.x + threadIdx.x) >> 5;
        int nwarps = (NODE_BLOCKS * blockDim.x) >> 5;

        float racc = 0.f;
        for (long long base = (long long)gwid * 32; base < N; base += (long long)nwarps * 32) {
            int idx   = (int)base + lane;
            bool valid = idx < N;
            float2 p = valid ? pred[idx] : make_float2(0.f, 0.f);
            if (valid) {
                float2 t = __ldcs(&targ[idx]);
                float dx = p.x - t.x, dy = p.y - t.y;
                racc += dx * dx + dy * dy;
            }
            int g  = valid ? __ldcs(&batch[idx]) : -1;
            int g0 = __shfl_sync(0xffffffffu, g, 0);
            unsigned vm = __ballot_sync(0xffffffffu, valid);
            bool uniform = __all_sync(0xffffffffu, (!valid) || (g == g0));
            if (uniform) {
                float sx = warpReduceF(valid ? p.x : 0.f);
                float sy = warpReduceF(valid ? p.y : 0.f);
                if (lane == 0 && vm) {
                    atomicAdd(&g_sumx[g0], sx);
                    atomicAdd(&g_sumy[g0], sy);
                    atomicAdd(&g_cnt [g0], (float)__popc(vm));
                }
            } else if (valid) {   // rare: warp straddles a graph boundary
                atomicAdd(&g_sumx[g], p.x);
                atomicAdd(&g_sumy[g], p.y);
                atomicAdd(&g_cnt [g], 1.f);
            }
        }
        blockAtomicAddD((double)racc, &g_recon, sh);
    } else if (blockIdx.x < NODE_BLOCKS + KL_BLOCKS) {
        // KL phase: 32 blocks cover GL = 8192 elements
        float kacc = 0.f;
        int b = blockIdx.x - NODE_BLOCKS;
        for (int i = b * blockDim.x + threadIdx.x; i < GL; i += KL_BLOCKS * blockDim.x) {
            float lv = logvar[i];
            float m  = mu[i];
            kacc += 1.0f + lv - m * m - __expf(lv);
        }
        blockAtomicAddD((double)kacc, &g_kl, sh);
    }

    // ------------- edge phase: work-stealing over chunks of int4 groups ------
    {
        const int* ej = ei + E;
        int E4 = E >> 2;
        const int4* ei4 = (const int4*)ei;
        const int4* ej4 = (const int4*)ej;
        unsigned nChunks = (unsigned)((E4 + CHUNK - 1) / CHUNK);

        float s2 = 0.f, sl = 0.f;

        while (true) {
            if (threadIdx.x == 0) s_chunk = atomicAdd(&g_ticket, 1u);
            __syncthreads();
            unsigned c = s_chunk;
            if (c >= nChunks) break;          // uniform across block

            int base = (int)c * CHUNK;
            int end  = base + CHUNK; if (end > E4) end = E4;

            for (int k = base + threadIdx.x; k < end; k += blockDim.x) {
                int4 a = __ldcs(&ei4[k]);
                int4 b = __ldcs(&ej4[k]);
                float2 pa0 = __ldg(&pred[a.x]); float2 pb0 = __ldg(&pred[b.x]);
                float2 pa1 = __ldg(&pred[a.y]); float2 pb1 = __ldg(&pred[b.y]);
                float2 pa2 = __ldg(&pred[a.z]); float2 pb2 = __ldg(&pred[b.z]);
                float2 pa3 = __ldg(&pred[a.w]); float2 pb3 = __ldg(&pred[b.w]);

                float dx0 = pa0.x - pb0.x, dy0 = pa0.y - pb0.y;
                float dx1 = pa1.x - pb1.x, dy1 = pa1.y - pb1.y;
                float dx2 = pa2.x - pb2.x, dy2 = pa2.y - pb2.y;
                float dx3 = pa3.x - pb3.x, dy3 = pa3.y - pb3.y;

                float d0 = dx0 * dx0 + dy0 * dy0;
                float d1 = dx1 * dx1 + dy1 * dy1;
                float d2 = dx2 * dx2 + dy2 * dy2;
                float d3 = dx3 * dx3 + dy3 * dy3;

                s2 += (d0 + d1) + (d2 + d3);
                sl += (sqrtf(d0) + sqrtf(d1)) + (sqrtf(d2) + sqrtf(d3));
            }
            __syncthreads();                  // done with s_chunk before rewrite
        }

        // tail (E % 4) — tiny or empty; every block strides it (idempotent split)
        for (int k = (E4 << 2) + (int)(blockIdx.x * blockDim.x + threadIdx.x);
             k < E; k += (int)(gridDim.x * blockDim.x)) {
            float2 pa = __ldg(&pred[__ldcs(&ei[k])]);
            float2 pb = __ldg(&pred[__ldcs(&ej[k])]);
            float dx = pa.x - pb.x, dy = pa.y - pb.y;
            float d = dx * dx + dy * dy;
            s2 += d;
            sl += sqrtf(d);
        }

        blockAtomicAddD((double)s2, &g_lap, sh);
        blockAtomicAddD((double)sl, &g_len, shl);
    }
}

// ---------------------------------------------------------------------------
// Compose: consume accumulators, write the scalar, then RESET all device
// state (incl. ticket counter) so the next graph replay starts clean.
// ---------------------------------------------------------------------------
__global__ void compose_kernel(const int* __restrict__ epoch_ptr,
                               float* __restrict__ out,
                               int E, int N) {
    __shared__ float shd[2];
    int lane = threadIdx.x & 31;
    int wid  = threadIdx.x >> 5;

    // Drift: one graph per thread (64 threads), float division
    {
        int g = threadIdx.x;
        float inv = 1.0f / g_cnt[g];
        float mx = g_sumx[g] * inv;
        float my = g_sumy[g] * inv;
        float d  = mx * mx + my * my;
        d = warpReduceF(d);
        if (lane == 0) shd[wid] = d;
    }
    __syncthreads();

    if (threadIdx.x == 0) {
        float drift = (shd[0] + shd[1]) / (float)NUM_GRAPHS;
        float kl    = -0.5f * (float)g_kl / (float)NUM_GRAPHS;

        float S2 = (float)g_lap;
        float S1 = (float)g_len;
        float fE = (float)E;
        float recon = (float)g_recon / (2.0f * (float)N);
        float lap   = S2 / fE;
        float var   = (S2 - S1 * (S1 / fE)) / (fE - 1.0f);

        int epoch = epoch_ptr ? *epoch_ptr : 5;
        float beta = (epoch < 10) ? ((float)epoch * 0.1f) : 1.0f;

        out[0] = recon + 0.1f * lap + 0.01f * drift + 0.1f * var + beta * kl;

        // reset scalar accumulators + ticket (same thread that read them)
        g_recon = 0.0; g_lap = 0.0; g_len = 0.0; g_kl = 0.0;
        g_ticket = 0u;
    }
    __syncthreads();   // all reads of g_sumx/y/cnt happened before this point

    // reset per-graph accumulators for the next replay
    g_sumx[threadIdx.x] = 0.f;
    g_sumy[threadIdx.x] = 0.f;
    g_cnt [threadIdx.x] = 0.f;
}

// ---------------------------------------------------------------------------
extern "C" void kernel_launch(void* const* d_in, const int* in_sizes, int n_in,
                              void* d_out, int out_size) {
    const float2* pred   = (const float2*)d_in[0];
    const float2* targ   = (const float2*)d_in[1];
    const int*    eidx   = (const int*)   d_in[2];
    const int*    batch  = (const int*)   d_in[3];
    const float*  mu     = (const float*) d_in[4];
    const float*  logvar = (const float*) d_in[5];
    const int*    epoch  = (n_in >= 7) ? (const int*)d_in[6] : nullptr;
    float*        out    = (float*)d_out;

    int N  = in_sizes[0] / 2;       // nodes
    int E  = in_sizes[2] / 2;       // edges
    int GL = in_sizes[4];           // NUM_GRAPHS * LATENT

    mega_kernel<<<1184, 256>>>(pred, targ, batch, mu, logvar, eidx, N, E, GL);
    compose_kernel<<<1, 64>>>(epoch, out, E, N);
}

// round 9
// speedup vs baseline: 1.3076x; 1.0878x over previous
#include <cuda_runtime.h>
#include <cuda_bf16.h>

// ---------------------------------------------------------------------------
// RIMDLoss fused loss — single-kernel persistent version.
// total = recon + 0.1*lap + 0.01*drift + 0.1*arap + beta*kl
//
// R7 (WIN): block-level work-stealing for the edge phase, 171.7 -> 143.1us,
//   confirming multi-CTA-spread tail theory.
// R8: (1) warp-level stealing (no per-chunk __syncthreads, 32x finer tail),
//     (2) compose folded into the mega kernel via last-block-done counter
//         -> ONE launch total. Device state self-resets for graph replays.
// Edge floor (L1tex wavefronts): ~110-115us.
// ---------------------------------------------------------------------------

#define NUM_GRAPHS  64
#define NODE_BLOCKS 128
#define KL_BLOCKS   32
#define WCHUNK      256    // int4-groups (4 edges each) per warp ticket

__device__ double   g_recon;   // sum (p-t)^2 over all elements
__device__ double   g_lap;     // sum d2 over edges (== sum len^2)
__device__ double   g_len;     // sum len over edges
__device__ double   g_kl;      // sum (1 + lv - mu^2 - exp(lv))
__device__ unsigned g_ticket;  // warp work-stealing counter
__device__ unsigned g_done;    // completed-blocks counter
__device__ float    g_sumx[NUM_GRAPHS];
__device__ float    g_sumy[NUM_GRAPHS];
__device__ float    g_cnt [NUM_GRAPHS];

__device__ __forceinline__ float warpReduceF(float v) {
    #pragma unroll
    for (int o = 16; o; o >>= 1) v += __shfl_down_sync(0xffffffffu, v, o);
    return v;
}
__device__ __forceinline__ double warpReduceD(double v) {
    #pragma unroll
    for (int o = 16; o; o >>= 1) v += __shfl_down_sync(0xffffffffu, v, o);
    return v;
}

// Block-reduce a double and atomically add into *dst.
__device__ __forceinline__ void blockAtomicAddD(double v, double* dst, double* sh) {
    int lane = threadIdx.x & 31;
    int wid  = threadIdx.x >> 5;
    v = warpReduceD(v);
    if (lane == 0) sh[wid] = v;
    __syncthreads();
    int nw = (blockDim.x + 31) >> 5;
    if (wid == 0) {
        double x = (lane < nw) ? sh[lane] : 0.0;
        x = warpReduceD(x);
        if (lane == 0) atomicAdd(dst, x);
    }
    __syncthreads();
}

// ---------------------------------------------------------------------------
__global__ __launch_bounds__(256)
void mega_kernel(const float2* __restrict__ pred,
                 const float2* __restrict__ targ,
                 const int*    __restrict__ batch,
                 const float*  __restrict__ mu,
                 const float*  __restrict__ logvar,
                 const int*    __restrict__ ei,   // row 0; row 1 at ei+E
                 const int*    __restrict__ epoch_ptr,
                 float*        __restrict__ out,
                 int N, int E, int GL) {
    __shared__ double   sh[32];
    __shared__ double   shl[32];
    __shared__ unsigned s_last;
    int lane = threadIdx.x & 31;

    // ------------- prologue: role-split node / KL (overlapped with edges) ----
    if (blockIdx.x < NODE_BLOCKS) {
        int gwid   = (blockIdx.x * blockDim.x + threadIdx.x) >> 5;
        int nwarps = (NODE_BLOCKS * blockDim.x) >> 5;

        float racc = 0.f;
        for (long long base = (long long)gwid * 32; base < N; base += (long long)nwarps * 32) {
            int idx   = (int)base + lane;
            bool valid = idx < N;
            float2 p = valid ? pred[idx] : make_float2(0.f, 0.f);
            if (valid) {
                float2 t = __ldcs(&targ[idx]);
                float dx = p.x - t.x, dy = p.y - t.y;
                racc += dx * dx + dy * dy;
            }
            int g  = valid ? __ldcs(&batch[idx]) : -1;
            int g0 = __shfl_sync(0xffffffffu, g, 0);
            unsigned vm = __ballot_sync(0xffffffffu, valid);
            bool uniform = __all_sync(0xffffffffu, (!valid) || (g == g0));
            if (uniform) {
                float sx = warpReduceF(valid ? p.x : 0.f);
                float sy = warpReduceF(valid ? p.y : 0.f);
                if (lane == 0 && vm) {
                    atomicAdd(&g_sumx[g0], sx);
                    atomicAdd(&g_sumy[g0], sy);
                    atomicAdd(&g_cnt [g0], (float)__popc(vm));
                }
            } else if (valid) {   // rare: warp straddles a graph boundary
                atomicAdd(&g_sumx[g], p.x);
                atomicAdd(&g_sumy[g], p.y);
                atomicAdd(&g_cnt [g], 1.f);
            }
        }
        blockAtomicAddD((double)racc, &g_recon, sh);
    } else if (blockIdx.x < NODE_BLOCKS + KL_BLOCKS) {
        float kacc = 0.f;
        int b = blockIdx.x - NODE_BLOCKS;
        for (int i = b * blockDim.x + threadIdx.x; i < GL; i += KL_BLOCKS * blockDim.x) {
            float lv = logvar[i];
            float m  = mu[i];
            kacc += 1.0f + lv - m * m - __expf(lv);
        }
        blockAtomicAddD((double)kacc, &g_kl, sh);
    }

    // ------------- edge phase: WARP-level work-stealing ----------------------
    {
        const int* ej = ei + E;
        int E4 = E >> 2;
        const int4* ei4 = (const int4*)ei;
        const int4* ej4 = (const int4*)ej;
        unsigned nChunks = (unsigned)((E4 + WCHUNK - 1) / WCHUNK);

        float s2 = 0.f, sl = 0.f;

        while (true) {
            unsigned c;
            if (lane == 0) c = atomicAdd(&g_ticket, 1u);
            c = __shfl_sync(0xffffffffu, c, 0);
            if (c >= nChunks) break;

            int base = (int)c * WCHUNK;
            int end  = base + WCHUNK; if (end > E4) end = E4;

            for (int k = base + lane; k < end; k += 32) {
                int4 a = __ldcs(&ei4[k]);
                int4 b = __ldcs(&ej4[k]);
                float2 pa0 = __ldg(&pred[a.x]); float2 pb0 = __ldg(&pred[b.x]);
                float2 pa1 = __ldg(&pred[a.y]); float2 pb1 = __ldg(&pred[b.y]);
                float2 pa2 = __ldg(&pred[a.z]); float2 pb2 = __ldg(&pred[b.z]);
                float2 pa3 = __ldg(&pred[a.w]); float2 pb3 = __ldg(&pred[b.w]);

                float dx0 = pa0.x - pb0.x, dy0 = pa0.y - pb0.y;
                float dx1 = pa1.x - pb1.x, dy1 = pa1.y - pb1.y;
                float dx2 = pa2.x - pb2.x, dy2 = pa2.y - pb2.y;
                float dx3 = pa3.x - pb3.x, dy3 = pa3.y - pb3.y;

                float d0 = dx0 * dx0 + dy0 * dy0;
                float d1 = dx1 * dx1 + dy1 * dy1;
                float d2 = dx2 * dx2 + dy2 * dy2;
                float d3 = dx3 * dx3 + dy3 * dy3;

                s2 += (d0 + d1) + (d2 + d3);
                sl += (sqrtf(d0) + sqrtf(d1)) + (sqrtf(d2) + sqrtf(d3));
            }
        }

        // tail (E % 4 — empty for E=16M, kept for generality)
        for (int k = (E4 << 2) + (int)(blockIdx.x * blockDim.x + threadIdx.x);
             k < E; k += (int)(gridDim.x * blockDim.x)) {
            float2 pa = __ldg(&pred[ei[k]]);
            float2 pb = __ldg(&pred[ej[k]]);
            float dx = pa.x - pb.x, dy = pa.y - pb.y;
            float d = dx * dx + dy * dy;
            s2 += d;
            sl += sqrtf(d);
        }

        blockAtomicAddD((double)s2, &g_lap, sh);
        blockAtomicAddD((double)sl, &g_len, shl);
    }

    // ------------- last-block-done: compose + reset --------------------------
    if (threadIdx.x == 0) {
        __threadfence();
        unsigned old = atomicAdd(&g_done, 1u);
        s_last = (old == gridDim.x - 1) ? 1u : 0u;
    }
    __syncthreads();
    if (s_last) {
        __shared__ float shd[2];
        int wid = threadIdx.x >> 5;

        if (threadIdx.x < NUM_GRAPHS) {
            int g = threadIdx.x;
            float inv = 1.0f / g_cnt[g];
            float mx = g_sumx[g] * inv;
            float my = g_sumy[g] * inv;
            float d  = mx * mx + my * my;
            d = warpReduceF(d);
            if (lane == 0) shd[wid] = d;
        }
        __syncthreads();

        if (threadIdx.x == 0) {
            float drift = (shd[0] + shd[1]) / (float)NUM_GRAPHS;
            float kl    = -0.5f * (float)g_kl / (float)NUM_GRAPHS;

            float S2 = (float)g_lap;
            float S1 = (float)g_len;
            float fE = (float)E;
            float recon = (float)g_recon / (2.0f * (float)N);
            float lap   = S2 / fE;
            float var   = (S2 - S1 * (S1 / fE)) / (fE - 1.0f);

            int epoch = epoch_ptr ? *epoch_ptr : 5;
            float beta = (epoch < 10) ? ((float)epoch * 0.1f) : 1.0f;

            out[0] = recon + 0.1f * lap + 0.01f * drift + 0.1f * var + beta * kl;

            // reset scalar state for the next graph replay
            g_recon = 0.0; g_lap = 0.0; g_len = 0.0; g_kl = 0.0;
            g_ticket = 0u; g_done = 0u;
        }
        __syncthreads();   // all reads of g_sumx/y/cnt done above
        if (threadIdx.x < NUM_GRAPHS) {
            g_sumx[threadIdx.x] = 0.f;
            g_sumy[threadIdx.x] = 0.f;
            g_cnt [threadIdx.x] = 0.f;
        }
    }
}

// ---------------------------------------------------------------------------
extern "C" void kernel_launch(void* const* d_in, const int* in_sizes, int n_in,
                              void* d_out, int out_size) {
    const float2* pred   = (const float2*)d_in[0];
    const float2* targ   = (const float2*)d_in[1];
    const int*    eidx   = (const int*)   d_in[2];
    const int*    batch  = (const int*)   d_in[3];
    const float*  mu     = (const float*) d_in[4];
    const float*  logvar = (const float*) d_in[5];
    const int*    epoch  = (n_in >= 7) ? (const int*)d_in[6] : nullptr;
    float*        out    = (float*)d_out;

    int N  = in_sizes[0] / 2;       // nodes
    int E  = in_sizes[2] / 2;       // edges
    int GL = in_sizes[4];           // NUM_GRAPHS * LATENT

    mega_kernel<<<1184, 256>>>(pred, targ, batch, mu, logvar, eidx,
                               epoch, out, N, E, GL);
}